// round 6
// baseline (speedup 1.0000x reference)
#include <cuda_runtime.h>

// Problem constants (fixed: B=65536, T=100, D_CP=2, D_FIN=3, HID=12, D_OUT=2)
#define BT_B 65536
#define BT_T 100

#define ROWS_PER_CTA 64      // 128 threads, 2 per row
#define WIN 10               // timesteps per staging window (10 windows total)
#define FIN_STRIDE 34        // 30 data floats + pad (8B-aligned rows, conflict-free)
#define OUT_STRIDE 28        // 20 data floats + pad (16B-aligned rows)

typedef unsigned long long u64;

__device__ __forceinline__ u64 pack2(float lo, float hi) {
    u64 r; asm("mov.b64 %0, {%1, %2};" : "=l"(r) : "f"(lo), "f"(hi)); return r;
}
__device__ __forceinline__ void unpack2(u64 v, float& lo, float& hi) {
    asm("mov.b64 {%0, %1}, %2;" : "=f"(lo), "=f"(hi) : "l"(v));
}
__device__ __forceinline__ u64 fma2(u64 a, u64 b, u64 c) {
    u64 d; asm("fma.rn.f32x2 %0, %1, %2, %3;" : "=l"(d) : "l"(a), "l"(b), "l"(c)); return d;
}
__device__ __forceinline__ float tanhapx(float x) {
    float r; asm("tanh.approx.f32 %0, %1;" : "=f"(r) : "f"(x)); return r;
}

__global__ __launch_bounds__(128, 7)
void deform_tracker_kernel(const float* __restrict__ cp,     // (B, T, 2)
                           const float* __restrict__ fin,    // (B, T, 3)
                           const float* __restrict__ Wr,     // (5, 12)
                           const float* __restrict__ br,     // (12,)
                           const float* __restrict__ Wo,     // (14, 2)
                           const float* __restrict__ bo,     // (2,)
                           float* __restrict__ out)          // (B, T, 2)
{
    __shared__ float sfin[ROWS_PER_CTA * FIN_STRIDE];   // staged finger window
    __shared__ float sout[ROWS_PER_CTA * OUT_STRIDE];   // staged output window

    const int tid  = threadIdx.x;
    const int lrow = tid >> 1;                 // local row 0..63
    const int half = tid & 1;                  // which 6 hidden units
    const int cbase = 6 * half;
    const int row0 = blockIdx.x * ROWS_PER_CTA;
    const int row  = row0 + lrow;

    // ---- Register-resident weights (own half of the hidden dim) ----
    u64 Wp[5][3];
    #pragma unroll
    for (int i = 0; i < 5; i++)
        #pragma unroll
        for (int k = 0; k < 3; k++)
            Wp[i][k] = pack2(__ldg(Wr + i * 12 + cbase + 2 * k),
                             __ldg(Wr + i * 12 + cbase + 2 * k + 1));

    float wu[6], wv[6];
    #pragma unroll
    for (int j = 0; j < 6; j++) {
        wu[j] = __ldg(Wo + (2 + cbase + j) * 2 + 0);
        wv[j] = __ldg(Wo + (2 + cbase + j) * 2 + 1);
    }
    const float w00 = __ldg(Wo + 0), w01 = __ldg(Wo + 1);
    const float w10 = __ldg(Wo + 2), w11 = __ldg(Wo + 3);
    const float bo0 = __ldg(bo + 0), bo1 = __ldg(bo + 1);

    // ---- Per-row invariants ----
    const float2 cp0 = *reinterpret_cast<const float2*>(cp + (size_t)row * (BT_T * 2));
    const float c0 = fmaf(cp0.x, w00, fmaf(cp0.y, w10, bo0));
    const float c1 = fmaf(cp0.x, w01, fmaf(cp0.y, w11, bo1));

    u64 base[3];
    {
        u64 p0 = pack2(c0, c0), p1 = pack2(c1, c1);
        #pragma unroll
        for (int k = 0; k < 3; k++) {
            u64 brp = pack2(__ldg(br + cbase + 2 * k), __ldg(br + cbase + 2 * k + 1));
            base[k] = fma2(p1, Wp[1][k], fma2(p0, Wp[0][k], brp));
        }
    }

    float u = cp0.x - c0, v = cp0.y - c1;

    const float2* fin2 = reinterpret_cast<const float2*>(fin);   // row stride 150 float2
    float2* out2 = reinterpret_cast<float2*>(out);               // row stride 100 float2

    #pragma unroll 1
    for (int w = 0; w < BT_T / WIN; w++) {
        // ---- Stage fin window: 64 rows x 15 float2, coalesced gmem -> SMEM ----
        #pragma unroll 1
        for (int i = tid; i < ROWS_PER_CTA * 15; i += 128) {
            int r = i / 15, j = i % 15;
            float2 val = fin2[(size_t)(row0 + r) * 150 + w * 15 + j];
            *reinterpret_cast<float2*>(&sfin[r * FIN_STRIDE + 2 * j]) = val;
        }
        __syncthreads();

        // ---- Compute WIN steps (5 chunks of 2) ----
        const float* myf = &sfin[lrow * FIN_STRIDE];
        float* myo = &sout[lrow * OUT_STRIDE];
        #pragma unroll
        for (int c = 0; c < WIN / 2; c++) {
            float2 g0 = *reinterpret_cast<const float2*>(myf + 6 * c + 0);
            float2 g1 = *reinterpret_cast<const float2*>(myf + 6 * c + 2);
            float2 g2 = *reinterpret_cast<const float2*>(myf + 6 * c + 4);
            float f[6] = {g0.x, g0.y, g1.x, g1.y, g2.x, g2.y};
            float res[4];

            #pragma unroll
            for (int s = 0; s < 2; s++) {
                // Off-chain partial: base + fin_t @ Wr[2:5]
                u64 px2 = pack2(f[3 * s + 0], f[3 * s + 0]);
                u64 px3 = pack2(f[3 * s + 1], f[3 * s + 1]);
                u64 px4 = pack2(f[3 * s + 2], f[3 * s + 2]);
                u64 part[3];
                #pragma unroll
                for (int k = 0; k < 3; k++)
                    part[k] = fma2(px4, Wp[4][k], fma2(px3, Wp[3][k], fma2(px2, Wp[2][k], base[k])));

                // Critical chain: + u*Wr0 + v*Wr1, tanh
                u64 pu = pack2(u, u), pv = pack2(v, v);
                float h[6];
                #pragma unroll
                for (int k = 0; k < 3; k++) {
                    u64 a = fma2(pv, Wp[1][k], fma2(pu, Wp[0][k], part[k]));
                    float a0, a1;
                    unpack2(a, a0, a1);
                    h[2 * k + 0] = tanhapx(a0);
                    h[2 * k + 1] = tanhapx(a1);
                }

                // Own half of the output dot
                float ua = h[0] * wu[0], ub = h[1] * wu[1];
                float va = h[0] * wv[0], vb = h[1] * wv[1];
                #pragma unroll
                for (int j = 2; j < 6; j += 2) {
                    ua = fmaf(h[j],     wu[j],     ua);
                    ub = fmaf(h[j + 1], wu[j + 1], ub);
                    va = fmaf(h[j],     wv[j],     va);
                    vb = fmaf(h[j + 1], wv[j + 1], vb);
                }
                float uo = ua + ub, vo = va + vb;

                // Exchange partner's partial; both threads hold full (u,v)
                float up = __shfl_xor_sync(0xFFFFFFFFu, uo, 1);
                float vp = __shfl_xor_sync(0xFFFFFFFFu, vo, 1);
                u = uo + up;
                v = vo + vp;

                res[2 * s + 0] = c0 + u;
                res[2 * s + 1] = c1 + v;
            }

            // Stage result chunk (alternate pair-thread; lockstep-identical values)
            if (half == (c & 1)) {
                *reinterpret_cast<float4*>(myo + 4 * c) =
                    make_float4(res[0], res[1], res[2], res[3]);
            }
        }
        __syncthreads();

        // ---- Flush out window: 64 rows x 10 float2, SMEM -> gmem coalesced ----
        #pragma unroll 1
        for (int i = tid; i < ROWS_PER_CTA * 10; i += 128) {
            int r = i / 10, j = i % 10;
            float2 val = *reinterpret_cast<const float2*>(&sout[r * OUT_STRIDE + 2 * j]);
            out2[(size_t)(row0 + r) * 100 + w * 10 + j] = val;
        }
        __syncthreads();
    }
}

extern "C" void kernel_launch(void* const* d_in, const int* in_sizes, int n_in,
                              void* d_out, int out_size) {
    const float* cp  = (const float*)d_in[0];  // control_point_input (B,T,2)
    const float* fin = (const float*)d_in[1];  // finger_input (B,T,3)
    const float* Wr  = (const float*)d_in[2];  // W_rnn (5,12)
    // d_in[3] = U_rnn — mathematically inert (hidden state reset each step)
    const float* br  = (const float*)d_in[4];  // b_rnn (12,)
    const float* Wo  = (const float*)d_in[5];  // W_out (14,2)
    const float* bo  = (const float*)d_in[6];  // b_out (2,)
    float* out = (float*)d_out;

    const int blocks = BT_B / ROWS_PER_CTA;    // 1024 = one wave at 7 CTAs/SM
    deform_tracker_kernel<<<blocks, 128>>>(cp, fin, Wr, br, Wo, bo, out);
}